// round 8
// baseline (speedup 1.0000x reference)
#include <cuda_runtime.h>
#include <cstdint>
#include <cstddef>

#define N_ALL 8192
#define N_SUP 2048
#define N_QRY 6144
#define D_IN  512
#define D_MOD 256
#define NCLS  64
#define KNN   10
#define NW    (N_ALL/32)     // 256 words per bitset row
#define SPLITS 8
#define CTILES (N_ALL/128/SPLITS)   // 8 column tiles of 128 per block

typedef unsigned long long ull;

// ---- scratch (device globals; no allocation APIs) ----
__device__ float    g_emb[N_ALL * D_MOD];                 // 8 MB
__device__ float    g_sq[N_ALL];
__device__ ull      g_part[(size_t)N_ALL * SPLITS * KNN]; // 5.2 MB partial top-k keys
__device__ int      g_topk[N_ALL * KNN];
__device__ unsigned g_adj[N_ALL * NW];                    // 8 MB bitset
__device__ float    g_deg[N_ALL];
__device__ float    g_lab0[N_ALL * NCLS];
__device__ float    g_lab1[N_ALL * NCLS];

// ============================================================
// 1) Embedding GEMM: [8192 x 512] @ [512 x 256] -> g_emb
// ============================================================
__global__ void embed_gemm(const float* __restrict__ sup,
                           const float* __restrict__ qry,
                           const float* __restrict__ W) {
    __shared__ float As[16][128];
    __shared__ float Bs[16][128];
    const int bn = blockIdx.x, bm = blockIdx.y;
    const int tid = threadIdx.x;
    const int tx = tid & 15, ty = tid >> 4;
    float acc[8][8];
    #pragma unroll
    for (int i = 0; i < 8; i++)
        #pragma unroll
        for (int j = 0; j < 8; j++) acc[i][j] = 0.f;

    for (int k0 = 0; k0 < D_IN; k0 += 16) {
        #pragma unroll
        for (int p = 0; p < 2; p++) {
            int m  = p * 64 + (tid >> 2);
            int c4 = tid & 3;
            int row = bm * 128 + m;
            const float* Ar = (row < N_SUP) ? (sup + (size_t)row * D_IN)
                                            : (qry + (size_t)(row - N_SUP) * D_IN);
            float4 v = *(const float4*)(Ar + k0 + c4 * 4);
            As[c4*4+0][m] = v.x; As[c4*4+1][m] = v.y;
            As[c4*4+2][m] = v.z; As[c4*4+3][m] = v.w;
        }
        #pragma unroll
        for (int p = 0; p < 2; p++) {
            int r = p * 8 + (tid >> 5);
            int c = (tid & 31) * 4;
            float4 v = *(const float4*)(W + (size_t)(k0 + r) * D_MOD + bn * 128 + c);
            *(float4*)&Bs[r][c] = v;
        }
        __syncthreads();
        #pragma unroll
        for (int k = 0; k < 16; k++) {
            float a[8], b[8];
            *(float4*)&a[0] = *(float4*)&As[k][ty*8];
            *(float4*)&a[4] = *(float4*)&As[k][ty*8+4];
            *(float4*)&b[0] = *(float4*)&Bs[k][tx*8];
            *(float4*)&b[4] = *(float4*)&Bs[k][tx*8+4];
            #pragma unroll
            for (int i = 0; i < 8; i++)
                #pragma unroll
                for (int j = 0; j < 8; j++)
                    acc[i][j] = fmaf(a[i], b[j], acc[i][j]);
        }
        __syncthreads();
    }
    #pragma unroll
    for (int i = 0; i < 8; i++) {
        int row = bm * 128 + ty * 8 + i;
        #pragma unroll
        for (int j = 0; j < 8; j += 4) {
            int col = bn * 128 + tx * 8 + j;
            *(float4*)&g_emb[(size_t)row * D_MOD + col] =
                make_float4(acc[i][j], acc[i][j+1], acc[i][j+2], acc[i][j+3]);
        }
    }
}

// ============================================================
// 2) Squared norms (one warp per row)
// ============================================================
__global__ void sqnorm_kernel() {
    int row  = blockIdx.x * 8 + (threadIdx.x >> 5);
    int lane = threadIdx.x & 31;
    float s = 0.f;
    #pragma unroll
    for (int c = lane; c < D_MOD; c += 32) {
        float v = g_emb[(size_t)row * D_MOD + c];
        s = fmaf(v, v, s);
    }
    #pragma unroll
    for (int o = 16; o; o >>= 1) s += __shfl_xor_sync(~0u, s, o);
    if (!lane) g_sq[row] = s;
}

// ============================================================
// 3) FUSED distance GEMM + per-row top-K (no 256MB dist matrix).
//    Grid (SPLITS, 64): block owns 128 rows x 1024 cols.
//    Per 128x128 tile: SGEMM -> distances staged in smem ->
//    2 threads/row keep persistent sorted top-10 in REGISTERS
//    (static-index insertion, no local-memory spill).
//    Key = (dist_bits<<32)|j reproduces jax.lax.top_k tie order.
// ============================================================
__device__ __forceinline__ void insert_key(ull loc[KNN], ull key) {
    if (key < loc[KNN-1]) {
        ull t = key;
        #pragma unroll
        for (int q = 0; q < KNN; q++) {
            ull cur = loc[q];
            bool lt = t < cur;
            loc[q] = lt ? t : cur;
            t      = lt ? cur : t;
        }
    }
}

__device__ __forceinline__ void scan_row(const float* __restrict__ dr,
                                         int colbase, int h, ull loc[KNN]) {
    #pragma unroll 4
    for (int s = 0; s < 64; s++) {
        int c = h + 2 * s;                       // parity-interleaved: conflict-free
        ull key = ((ull)__float_as_uint(dr[c]) << 32) | (unsigned)(colbase + c);
        insert_key(loc, key);
    }
}

__global__ void dist_topk_fused() {
    // 33280-byte aliased pool: [As|Bs] during GEMM, Ds during merge, P at end.
    __shared__ __align__(16) unsigned char pool[33280];
    float (*As)[128] = (float (*)[128])pool;             //  8 KB
    float (*Bs)[128] = (float (*)[128])(pool + 8192);    //  8 KB
    float (*Ds)[130] = (float (*)[130])pool;             // 64 rows x 130 floats
    ull*   P         = (ull*)pool;                       // 128*2*10 keys = 20 KB

    const int split = blockIdx.x;
    const int bm    = blockIdx.y;
    const int tid = threadIdx.x;
    const int tx = tid & 15, ty = tid >> 4;
    const int rowbase = bm * 128;

    ull loc[KNN];
    #pragma unroll
    for (int i = 0; i < KNN; i++) loc[i] = ~0ull;
    const int myrow_loc = (tid < 128) ? (tid >> 1) : 64 + ((tid - 128) >> 1);
    const int myhalf    = tid & 1;

    float sqi[8];
    #pragma unroll
    for (int i = 0; i < 8; i++) sqi[i] = g_sq[rowbase + ty * 8 + i];

    for (int tile = 0; tile < CTILES; tile++) {
        const int colbase = split * (CTILES * 128) + tile * 128;

        float acc[8][8];
        #pragma unroll
        for (int i = 0; i < 8; i++)
            #pragma unroll
            for (int j = 0; j < 8; j++) acc[i][j] = 0.f;

        for (int k0 = 0; k0 < D_MOD; k0 += 16) {
            #pragma unroll
            for (int p = 0; p < 2; p++) {
                int m  = p * 64 + (tid >> 2);
                int c4 = tid & 3;
                float4 va = *(const float4*)&g_emb[(size_t)(rowbase + m) * D_MOD + k0 + c4*4];
                As[c4*4+0][m] = va.x; As[c4*4+1][m] = va.y;
                As[c4*4+2][m] = va.z; As[c4*4+3][m] = va.w;
                float4 vb = *(const float4*)&g_emb[(size_t)(colbase + m) * D_MOD + k0 + c4*4];
                Bs[c4*4+0][m] = vb.x; Bs[c4*4+1][m] = vb.y;
                Bs[c4*4+2][m] = vb.z; Bs[c4*4+3][m] = vb.w;
            }
            __syncthreads();
            #pragma unroll
            for (int k = 0; k < 16; k++) {
                float a[8], b[8];
                *(float4*)&a[0] = *(float4*)&As[k][ty*8];
                *(float4*)&a[4] = *(float4*)&As[k][ty*8+4];
                *(float4*)&b[0] = *(float4*)&Bs[k][tx*8];
                *(float4*)&b[4] = *(float4*)&Bs[k][tx*8+4];
                #pragma unroll
                for (int i = 0; i < 8; i++)
                    #pragma unroll
                    for (int j = 0; j < 8; j++)
                        acc[i][j] = fmaf(a[i], b[j], acc[i][j]);
            }
            __syncthreads();
        }

        float sqj[8];
        #pragma unroll
        for (int j = 0; j < 8; j++) sqj[j] = g_sq[colbase + tx * 8 + j];

        // ---- Phase A: rows 0..63 of the tile ----
        if (ty < 8) {
            #pragma unroll
            for (int i = 0; i < 8; i++) {
                int r = ty * 8 + i;
                #pragma unroll
                for (int j = 0; j < 8; j += 2) {
                    float d0 = sqrtf(fmaxf(sqi[i] + sqj[j]   - 2.0f * acc[i][j],   0.f));
                    float d1 = sqrtf(fmaxf(sqi[i] + sqj[j+1] - 2.0f * acc[i][j+1], 0.f));
                    *(float2*)&Ds[r][tx * 8 + j] = make_float2(d0, d1);
                }
            }
        }
        __syncthreads();
        if (tid < 128) scan_row(Ds[tid >> 1], colbase, myhalf, loc);
        __syncthreads();

        // ---- Phase B: rows 64..127 of the tile ----
        if (ty >= 8) {
            #pragma unroll
            for (int i = 0; i < 8; i++) {
                int r = (ty - 8) * 8 + i;
                #pragma unroll
                for (int j = 0; j < 8; j += 2) {
                    float d0 = sqrtf(fmaxf(sqi[i] + sqj[j]   - 2.0f * acc[i][j],   0.f));
                    float d1 = sqrtf(fmaxf(sqi[i] + sqj[j+1] - 2.0f * acc[i][j+1], 0.f));
                    *(float2*)&Ds[r][tx * 8 + j] = make_float2(d0, d1);
                }
            }
        }
        __syncthreads();
        if (tid >= 128) scan_row(Ds[(tid - 128) >> 1], colbase, myhalf, loc);
        __syncthreads();
    }

    // ---- emit per-row partial top-10 for this column split ----
    #pragma unroll
    for (int i = 0; i < KNN; i++)
        P[(myrow_loc * 2 + myhalf) * KNN + i] = loc[i];
    __syncthreads();
    if (myhalf == 0) {
        const ull* La = &P[(myrow_loc * 2 + 0) * KNN];
        const ull* Lb = &P[(myrow_loc * 2 + 1) * KNN];
        int ia = 0, ib = 0;
        ull* out = &g_part[((size_t)(rowbase + myrow_loc) * SPLITS + split) * KNN];
        #pragma unroll
        for (int o = 0; o < KNN; o++) {
            ull a = (ia < KNN) ? La[ia] : ~0ull;
            ull b = (ib < KNN) ? Lb[ib] : ~0ull;
            if (a < b) { out[o] = a; ia++; } else { out[o] = b; ib++; }
        }
    }
}

// ============================================================
// 4) Merge SPLITS partial lists -> final top-10 indices per row
// ============================================================
__global__ void topk_merge() {
    int row = blockIdx.x * 256 + threadIdx.x;   // 8192 threads
    ull loc[KNN];
    #pragma unroll
    for (int i = 0; i < KNN; i++) loc[i] = ~0ull;
    const ull* __restrict__ p = &g_part[(size_t)row * SPLITS * KNN];
    for (int s = 0; s < SPLITS * KNN; s++) insert_key(loc, p[s]);
    #pragma unroll
    for (int i = 0; i < KNN; i++)
        g_topk[row * KNN + i] = (int)(loc[i] & 0xffffffffu);
}

// ============================================================
// 5) Adjacency bitset (symmetrized), degree
// ============================================================
__global__ void zero_adj() {
    int i = blockIdx.x * 256 + threadIdx.x;
    g_adj[i] = 0u;
}
__global__ void build_adj() {
    int e = blockIdx.x * 256 + threadIdx.x;
    if (e >= N_ALL * KNN) return;
    int i = e / KNN;
    int j = g_topk[e];
    atomicOr(&g_adj[(size_t)i * NW + (j >> 5)], 1u << (j & 31));
    atomicOr(&g_adj[(size_t)j * NW + (i >> 5)], 1u << (i & 31));
}
__global__ void degree_kernel() {
    int row  = blockIdx.x * 8 + (threadIdx.x >> 5);
    int lane = threadIdx.x & 31;
    int c = 0;
    #pragma unroll
    for (int w = lane; w < NW; w += 32) c += __popc(g_adj[(size_t)row * NW + w]);
    #pragma unroll
    for (int o = 16; o; o >>= 1) c += __shfl_xor_sync(~0u, c, o);
    if (!lane) g_deg[row] = (float)c;
}

// ============================================================
// 6) Label propagation (3 iterations). trans = adj/deg (row).
// ============================================================
__global__ void init_labels(const int* __restrict__ slab) {
    int i = blockIdx.x * 256 + threadIdx.x;
    int row = i >> 6, c = i & 63;
    g_lab0[i] = (row < N_SUP && slab[row] == c) ? 1.f : 0.f;
}
__global__ void propagate(int iter) {
    const float* __restrict__ lin  = (iter & 1) ? g_lab1 : g_lab0;
    float* __restrict__       lout = (iter & 1) ? g_lab0 : g_lab1;
    const int row = blockIdx.x;
    const int c   = threadIdx.x;   // 64 threads = 64 classes
    __shared__ unsigned w[NW];
    for (int k = c; k < NW; k += 64) w[k] = g_adj[(size_t)row * NW + k];
    __syncthreads();
    const float t = 1.0f / g_deg[row];
    float acc = 0.f;
    for (int k = 0; k < NW; k++) {
        unsigned m = w[k];
        while (m) {
            int b = __ffs(m) - 1;
            m &= m - 1;
            int j = (k << 5) | b;
            acc = fmaf(t, lin[(size_t)j * NCLS + c], acc);
        }
    }
    lout[(size_t)row * NCLS + c] = acc;
}

// ============================================================
// 7) Argmax (first-max tie-break) + one-hot output for query rows
// ============================================================
__global__ void out_kernel(float* __restrict__ out) {
    int r    = blockIdx.x * 4 + (threadIdx.x >> 5);   // 6144 rows
    int lane = threadIdx.x & 31;
    const float* L = &g_lab1[(size_t)(r + N_SUP) * NCLS];
    float v0 = L[lane], v1 = L[lane + 32];
    float bv; int bi;
    if (v1 > v0) { bv = v1; bi = lane + 32; } else { bv = v0; bi = lane; }
    #pragma unroll
    for (int o = 16; o; o >>= 1) {
        float ov = __shfl_xor_sync(~0u, bv, o);
        int   oi = __shfl_xor_sync(~0u, bi, o);
        if (ov > bv || (ov == bv && oi < bi)) { bv = ov; bi = oi; }
    }
    out[(size_t)r * NCLS + lane]      = (lane == bi)      ? 1.f : 0.f;
    out[(size_t)r * NCLS + 32 + lane] = (lane + 32 == bi) ? 1.f : 0.f;
}

// ============================================================
// launch
// ============================================================
extern "C" void kernel_launch(void* const* d_in, const int* in_sizes, int n_in,
                              void* d_out, int out_size) {
    const float* sup  = (const float*)d_in[0];   // (1, 2048, 512)
    const float* qry  = (const float*)d_in[1];   // (1, 6144, 512)
    const int*   slab = (const int*)d_in[2];     // (2048,)
    const float* W    = (const float*)d_in[3];   // (512, 256)
    float* out        = (float*)d_out;           // (1, 6144, 64)

    embed_gemm<<<dim3(D_MOD / 128, N_ALL / 128), 256>>>(sup, qry, W);
    sqnorm_kernel<<<N_ALL / 8, 256>>>();
    dist_topk_fused<<<dim3(SPLITS, N_ALL / 128), 256>>>();
    topk_merge<<<N_ALL / 256, 256>>>();
    zero_adj<<<(N_ALL * NW) / 256, 256>>>();
    build_adj<<<(N_ALL * KNN + 255) / 256, 256>>>();
    degree_kernel<<<N_ALL / 8, 256>>>();
    init_labels<<<(N_ALL * NCLS) / 256, 256>>>(slab);
    propagate<<<N_ALL, 64>>>(0);   // lab0 -> lab1
    propagate<<<N_ALL, 64>>>(1);   // lab1 -> lab0
    propagate<<<N_ALL, 64>>>(0);   // lab0 -> lab1
    out_kernel<<<N_QRY / 4, 128>>>(out);
}